// round 1
// baseline (speedup 1.0000x reference)
#include <cuda_runtime.h>
#include <math.h>

// ---------------- problem constants ----------------
#define BATCH   64
#define NPATCH  196
#define NVIS    49
#define ENC     768
#define DEC     512
#define FFN     2048
#define OUTD    3072      // 16*16*12
#define NLAYERS 8
#define NHEADS  16
#define HD      32
#define IMG     224
#define CIN     12
#define PS      16

#define TOK_FULL (BATCH*NPATCH)   // 12544
#define TOK_VIS  (BATCH*NVIS)     // 3136

// ---------------- scratch (device globals; no allocation) ----------------
__device__ float g_vp  [TOK_VIS * OUTD];    // gathered visible patches
__device__ float g_enc [TOK_VIS * ENC];     // encoder output (also 2nd model output)
__device__ float g_dec [TOK_VIS * DEC];     // enc2dec
__device__ float g_h   [TOK_FULL * DEC];    // running hidden state
__device__ float g_qkv [TOK_FULL * 3*DEC];
__device__ float g_attn[TOK_FULL * DEC];
__device__ float g_ffn [TOK_FULL * FFN];
__device__ float g_tmp [TOK_FULL * DEC];
__device__ int   g_vis_idx[TOK_VIS];
__device__ int   g_slot[TOK_FULL];          // -1 => masked (use mask_token)
__device__ int   g_mode;                    // mask dtype: 0=int32 1=uint8 2=float32

// ---------------- mask dtype detection (bool serialization is ambiguous) ----
__global__ void detect_mask_mode(const void* mask) {
    if (threadIdx.x != 0 || blockIdx.x != 0) return;
    // try int32 (values 0/1, row0 sums to 147 masked)
    {
        const int* p = (const int*)mask;
        bool ok = true; int s = 0;
        for (int i = 0; i < NPATCH; i++) { int v = p[i]; if (v != 0 && v != 1) { ok = false; break; } s += v; }
        if (ok && s == NPATCH - NVIS) { g_mode = 0; return; }
    }
    // try uint8 (any nonzero = true)
    {
        const unsigned char* p = (const unsigned char*)mask;
        int s = 0;
        for (int i = 0; i < NPATCH; i++) s += (p[i] != 0);
        if (s == NPATCH - NVIS) { g_mode = 1; return; }
    }
    g_mode = 2; // float32
}

__global__ void build_indices(const void* mask) {
    int b = blockIdx.x;
    if (threadIdx.x != 0) return;
    int mode = g_mode;
    const int*           pi = (const int*)mask;
    const unsigned char* pb = (const unsigned char*)mask;
    const float*         pf = (const float*)mask;
    int cnt = 0;
    for (int n = 0; n < NPATCH; n++) {
        int idx = b * NPATCH + n;
        bool m;
        if (mode == 0)      m = (pi[idx] != 0);
        else if (mode == 1) m = (pb[idx] != 0);
        else                m = (pf[idx] != 0.0f);
        if (!m) {
            if (cnt < NVIS) g_vis_idx[b * NVIS + cnt] = n;
            g_slot[idx] = cnt;
            cnt++;
        } else {
            g_slot[idx] = -1;
        }
    }
}

// ---------------- gather visible patches (unfold order: c, ph, pw) ----------
__global__ void gather_patches(const float* __restrict__ x) {
    int idx = blockIdx.x * blockDim.x + threadIdx.x;
    if (idx >= TOK_VIS * OUTD) return;
    int f  = idx % OUTD;
    int bv = idx / OUTD;
    int b  = bv / NVIS;
    int n  = g_vis_idx[bv];
    int c  = f >> 8;          // f / 256
    int r  = f & 255;
    int ph = r >> 4, pw = r & 15;
    int hp = n / 14, wp = n % 14;
    g_vp[idx] = x[(((size_t)(b * CIN + c)) * IMG + hp * PS + ph) * IMG + wp * PS + pw];
}

// ---------------- SGEMM 128x128x8, 8x8 register tile ----------------
// C[M,N] = A[M,K] @ B[K,N] + bias[N]  (+gelu | +residual)
// Requires: N % 128 == 0, K % 8 == 0 (true for all GEMMs here). M guarded.
template<int EPI>  // 0=none 1=gelu(exact) 2=add residual
__global__ __launch_bounds__(256)
void sgemm(const float* __restrict__ A, const float* __restrict__ B,
           const float* __restrict__ bias, const float* __restrict__ R,
           float* __restrict__ C, int M, int N, int K) {
    const int BM = 128, BN = 128, BK = 8;
    __shared__ float As[BK][BM];
    __shared__ float Bs[BK][BN];
    int tid = threadIdx.x;
    int tx = tid & 15, ty = tid >> 4;
    int rowBase = blockIdx.y * BM;
    int colBase = blockIdx.x * BN;
    int aRow = tid >> 1;
    int aK   = (tid & 1) * 4;
    int bK   = tid >> 5;
    int bCol = (tid & 31) * 4;

    float acc[8][8];
    #pragma unroll
    for (int i = 0; i < 8; i++)
        #pragma unroll
        for (int j = 0; j < 8; j++) acc[i][j] = 0.f;

    for (int k0 = 0; k0 < K; k0 += BK) {
        int gRow = rowBase + aRow;
        float4 av = make_float4(0.f, 0.f, 0.f, 0.f);
        if (gRow < M) av = *(const float4*)(A + (size_t)gRow * K + k0 + aK);
        As[aK + 0][aRow] = av.x; As[aK + 1][aRow] = av.y;
        As[aK + 2][aRow] = av.z; As[aK + 3][aRow] = av.w;
        float4 bv = *(const float4*)(B + (size_t)(k0 + bK) * N + colBase + bCol);
        *(float4*)(&Bs[bK][bCol]) = bv;
        __syncthreads();
        #pragma unroll
        for (int k = 0; k < BK; k++) {
            float ra[8], rb[8];
            #pragma unroll
            for (int i = 0; i < 8; i++) ra[i] = As[k][ty * 8 + i];
            #pragma unroll
            for (int j = 0; j < 8; j++) rb[j] = Bs[k][tx * 8 + j];
            #pragma unroll
            for (int i = 0; i < 8; i++)
                #pragma unroll
                for (int j = 0; j < 8; j++)
                    acc[i][j] = fmaf(ra[i], rb[j], acc[i][j]);
        }
        __syncthreads();
    }

    #pragma unroll
    for (int i = 0; i < 8; i++) {
        int gRow = rowBase + ty * 8 + i;
        if (gRow >= M) continue;
        #pragma unroll
        for (int j = 0; j < 8; j++) {
            int gCol = colBase + tx * 8 + j;
            float v = acc[i][j] + bias[gCol];
            if (EPI == 1) v = 0.5f * v * (1.0f + erff(v * 0.70710678118654752f));
            if (EPI == 2) v += R[(size_t)gRow * N + gCol];
            C[(size_t)gRow * N + gCol] = v;
        }
    }
}

// ---------------- mask-token assembly + pos embed ----------------
__global__ void assemble(const float* __restrict__ mask_token,
                         const float* __restrict__ pos) {
    int idx = blockIdx.x * blockDim.x + threadIdx.x;
    if (idx >= TOK_FULL * DEC) return;
    int d  = idx & (DEC - 1);
    int bn = idx >> 9;
    int n  = bn % NPATCH;
    int b  = bn / NPATCH;
    int sl = g_slot[bn];
    float v = (sl < 0) ? mask_token[d] : g_dec[(size_t)(b * NVIS + sl) * DEC + d];
    g_h[idx] = v + pos[n * DEC + d];
}

// ---------------- flash-style attention, one block per (b, head) ----------
__global__ __launch_bounds__(224)
void attn_kernel(const float* __restrict__ qkv, float* __restrict__ out) {
    const int S = NPATCH;
    int b = blockIdx.x >> 4;
    int h = blockIdx.x & 15;
    int tid = threadIdx.x;
    __shared__ float Kt[64][HD];
    __shared__ float Vt[64][HD];

    float q[HD];
    const float* qbase = qkv + (size_t)(b * S) * (3 * DEC) + h * HD;
    if (tid < S) {
        const float* qp = qbase + (size_t)tid * (3 * DEC);
        #pragma unroll
        for (int k = 0; k < HD; k++) q[k] = qp[k];
    }
    float o[HD];
    #pragma unroll
    for (int k = 0; k < HD; k++) o[k] = 0.f;
    float m = -1e30f, s = 0.f;
    const float scale = 0.17677669529663689f; // 1/sqrt(32)

    for (int j0 = 0; j0 < S; j0 += 64) {
        int jn = min(64, S - j0);
        for (int idx = tid; idx < jn * HD; idx += blockDim.x) {
            int jj = idx >> 5, kk = idx & 31;
            const float* base = qkv + (size_t)(b * S + j0 + jj) * (3 * DEC) + h * HD;
            Kt[jj][kk] = base[DEC + kk];
            Vt[jj][kk] = base[2 * DEC + kk];
        }
        __syncthreads();
        if (tid < S) {
            for (int jj = 0; jj < jn; jj++) {
                float d = 0.f;
                #pragma unroll
                for (int k = 0; k < HD; k++) d = fmaf(q[k], Kt[jj][k], d);
                d *= scale;
                float nm = fmaxf(m, d);
                float p    = __expf(d - nm);
                float corr = __expf(m - nm);
                s = s * corr + p;
                #pragma unroll
                for (int k = 0; k < HD; k++) o[k] = fmaf(o[k], corr, p * Vt[jj][k]);
                m = nm;
            }
        }
        __syncthreads();
    }
    if (tid < S) {
        float inv = 1.f / s;
        float* op = out + (size_t)(b * S + tid) * DEC + h * HD;
        #pragma unroll
        for (int k = 0; k < HD; k++) op[k] = o[k] * inv;
    }
}

// ---------------- layernorm over last dim 512 ----------------
__global__ __launch_bounds__(128)
void ln_kernel(const float* __restrict__ X, const float* __restrict__ g,
               const float* __restrict__ bta, float* __restrict__ Y) {
    int row = blockIdx.x;
    int tid = threadIdx.x;
    const float* x = X + (size_t)row * DEC;
    float v[4];
    float sum = 0.f, sq = 0.f;
    #pragma unroll
    for (int i = 0; i < 4; i++) {
        v[i] = x[tid + i * 128];
        sum += v[i];
        sq  += v[i] * v[i];
    }
    #pragma unroll
    for (int o = 16; o > 0; o >>= 1) {
        sum += __shfl_xor_sync(0xffffffffu, sum, o);
        sq  += __shfl_xor_sync(0xffffffffu, sq,  o);
    }
    __shared__ float s1[4], s2[4];
    int w = tid >> 5;
    if ((tid & 31) == 0) { s1[w] = sum; s2[w] = sq; }
    __syncthreads();
    float tot  = s1[0] + s1[1] + s1[2] + s1[3];
    float tot2 = s2[0] + s2[1] + s2[2] + s2[3];
    float mean = tot * (1.f / DEC);
    float var  = tot2 * (1.f / DEC) - mean * mean;
    float r = rsqrtf(var + 1e-5f);
    float* y = Y + (size_t)row * DEC;
    #pragma unroll
    for (int i = 0; i < 4; i++) {
        int c = tid + i * 128;
        y[c] = (v[i] - mean) * r * g[c] + bta[c];
    }
}

// ---------------- host orchestration ----------------
static void launch_gemm(int epi, const float* A, const float* B, const float* bias,
                        const float* R, float* C, int M, int N, int K) {
    dim3 grid(N / 128, (M + 127) / 128);
    if (epi == 0)      sgemm<0><<<grid, 256>>>(A, B, bias, R, C, M, N, K);
    else if (epi == 1) sgemm<1><<<grid, 256>>>(A, B, bias, R, C, M, N, K);
    else               sgemm<2><<<grid, 256>>>(A, B, bias, R, C, M, N, K);
}

extern "C" void kernel_launch(void* const* d_in, const int* in_sizes, int n_in,
                              void* d_out, int out_size) {
    const float* x          = (const float*)d_in[0];
    const void*  mask       = d_in[1];
    /* d_in[2] = n_visible (fixed 49) */
    const float* Wp         = (const float*)d_in[3];
    const float* bp         = (const float*)d_in[4];
    const float* We2d       = (const float*)d_in[5];
    const float* be2d       = (const float*)d_in[6];
    const float* mask_token = (const float*)d_in[7];
    const float* pos        = (const float*)d_in[8];
    const float* Wqkv       = (const float*)d_in[9];
    const float* bqkv       = (const float*)d_in[10];
    const float* Wo         = (const float*)d_in[11];
    const float* bo         = (const float*)d_in[12];
    const float* ln1g       = (const float*)d_in[13];
    const float* ln1b       = (const float*)d_in[14];
    const float* W1         = (const float*)d_in[15];
    const float* b1         = (const float*)d_in[16];
    const float* W2         = (const float*)d_in[17];
    const float* b2         = (const float*)d_in[18];
    const float* ln2g       = (const float*)d_in[19];
    const float* ln2b       = (const float*)d_in[20];
    const float* Wr         = (const float*)d_in[21];
    const float* br         = (const float*)d_in[22];
    float* out = (float*)d_out;

    float *p_vp, *p_enc, *p_dec, *p_h, *p_qkv, *p_attn, *p_ffn, *p_tmp;
    cudaGetSymbolAddress((void**)&p_vp,  g_vp);
    cudaGetSymbolAddress((void**)&p_enc, g_enc);
    cudaGetSymbolAddress((void**)&p_dec, g_dec);
    cudaGetSymbolAddress((void**)&p_h,   g_h);
    cudaGetSymbolAddress((void**)&p_qkv, g_qkv);
    cudaGetSymbolAddress((void**)&p_attn,g_attn);
    cudaGetSymbolAddress((void**)&p_ffn, g_ffn);
    cudaGetSymbolAddress((void**)&p_tmp, g_tmp);

    // indices
    detect_mask_mode<<<1, 32>>>(mask);
    build_indices<<<BATCH, 32>>>(mask);

    // patchify + gather visible
    {
        int total = TOK_VIS * OUTD;
        gather_patches<<<(total + 255) / 256, 256>>>(x);
    }

    // encoder projection: [3136,3072] @ [3072,768]
    launch_gemm(0, p_vp, Wp, bp, nullptr, p_enc, TOK_VIS, ENC, OUTD);
    // enc -> dec: [3136,768] @ [768,512]
    launch_gemm(0, p_enc, We2d, be2d, nullptr, p_dec, TOK_VIS, DEC, ENC);

    // assemble full sequence with mask tokens + pos embed
    {
        int total = TOK_FULL * DEC;
        assemble<<<(total + 255) / 256, 256>>>(mask_token, pos);
    }

    // decoder layers
    for (int l = 0; l < NLAYERS; l++) {
        const float* Wqkv_l = Wqkv + (size_t)l * DEC * 3 * DEC;
        const float* bqkv_l = bqkv + (size_t)l * 3 * DEC;
        const float* Wo_l   = Wo   + (size_t)l * DEC * DEC;
        const float* bo_l   = bo   + (size_t)l * DEC;
        const float* W1_l   = W1   + (size_t)l * DEC * FFN;
        const float* b1_l   = b1   + (size_t)l * FFN;
        const float* W2_l   = W2   + (size_t)l * FFN * DEC;
        const float* b2_l   = b2   + (size_t)l * DEC;

        launch_gemm(0, p_h, Wqkv_l, bqkv_l, nullptr, p_qkv, TOK_FULL, 3 * DEC, DEC);
        attn_kernel<<<BATCH * NHEADS, 224>>>(p_qkv, p_attn);
        launch_gemm(2, p_attn, Wo_l, bo_l, p_h, p_tmp, TOK_FULL, DEC, DEC);
        ln_kernel<<<TOK_FULL, 128>>>(p_tmp, ln1g + (size_t)l * DEC, ln1b + (size_t)l * DEC, p_h);

        launch_gemm(1, p_h, W1_l, b1_l, nullptr, p_ffn, TOK_FULL, FFN, DEC);
        launch_gemm(2, p_ffn, W2_l, b2_l, p_h, p_tmp, TOK_FULL, DEC, FFN);
        ln_kernel<<<TOK_FULL, 128>>>(p_tmp, ln2g + (size_t)l * DEC, ln2b + (size_t)l * DEC, p_h);
    }

    // reconstruction: [12544,512] @ [512,3072] -> d_out[0 : 38535168]
    launch_gemm(0, p_h, Wr, br, nullptr, out, TOK_FULL, OUTD, DEC);

    // second output: encoded [3136,768] appended after reconstructed
    const long long recon_elems = (long long)TOK_FULL * OUTD;       // 38,535,168
    const long long enc_elems   = (long long)TOK_VIS * ENC;         //  2,408,448
    if ((long long)out_size >= recon_elems + enc_elems) {
        cudaMemcpyAsync(out + recon_elems, p_enc, enc_elems * sizeof(float),
                        cudaMemcpyDeviceToDevice, 0);
    }
}

// round 3
// speedup vs baseline: 2.7998x; 2.7998x over previous
#include <cuda_runtime.h>
#include <cstdint>
#include <math.h>

// ---------------- problem constants ----------------
#define BATCH   64
#define NPATCH  196
#define NVIS    49
#define ENC     768
#define DEC     512
#define FFN     2048
#define OUTD    3072      // 16*16*12
#define NLAYERS 8
#define NHEADS  16
#define HD      32
#define IMG     224
#define CIN     12
#define PS      16

#define TOK_FULL (BATCH*NPATCH)   // 12544
#define TOK_VIS  (BATCH*NVIS)     // 3136

// ---------------- scratch (device globals; no allocation) ----------------
__device__ float g_vp  [TOK_VIS * OUTD];
__device__ float g_enc [TOK_VIS * ENC];
__device__ float g_dec [TOK_VIS * DEC];
__device__ float g_h   [TOK_FULL * DEC];
__device__ float g_qkv [TOK_FULL * 3*DEC];
__device__ float g_attn[TOK_FULL * DEC];
__device__ float g_ffn [TOK_FULL * FFN];
__device__ float g_tmp [TOK_FULL * DEC];
__device__ int   g_vis_idx[TOK_VIS];
__device__ int   g_slot[TOK_FULL];
__device__ int   g_mode;

// ---------------- mask dtype detection ----------------
__global__ void detect_mask_mode(const void* mask) {
    if (threadIdx.x != 0 || blockIdx.x != 0) return;
    {
        const int* p = (const int*)mask;
        bool ok = true; int s = 0;
        for (int i = 0; i < NPATCH; i++) { int v = p[i]; if (v != 0 && v != 1) { ok = false; break; } s += v; }
        if (ok && s == NPATCH - NVIS) { g_mode = 0; return; }
    }
    {
        const unsigned char* p = (const unsigned char*)mask;
        int s = 0;
        for (int i = 0; i < NPATCH; i++) s += (p[i] != 0);
        if (s == NPATCH - NVIS) { g_mode = 1; return; }
    }
    g_mode = 2;
}

__global__ void build_indices(const void* mask) {
    int b = blockIdx.x;
    if (threadIdx.x != 0) return;
    int mode = g_mode;
    const int*           pi = (const int*)mask;
    const unsigned char* pb = (const unsigned char*)mask;
    const float*         pf = (const float*)mask;
    int cnt = 0;
    for (int n = 0; n < NPATCH; n++) {
        int idx = b * NPATCH + n;
        bool m;
        if (mode == 0)      m = (pi[idx] != 0);
        else if (mode == 1) m = (pb[idx] != 0);
        else                m = (pf[idx] != 0.0f);
        if (!m) {
            if (cnt < NVIS) g_vis_idx[b * NVIS + cnt] = n;
            g_slot[idx] = cnt;
            cnt++;
        } else {
            g_slot[idx] = -1;
        }
    }
}

// ---------------- gather visible patches ----------------
__global__ void gather_patches(const float* __restrict__ x) {
    int idx = blockIdx.x * blockDim.x + threadIdx.x;
    if (idx >= TOK_VIS * OUTD) return;
    int f  = idx % OUTD;
    int bv = idx / OUTD;
    int b  = bv / NVIS;
    int n  = g_vis_idx[bv];
    int c  = f >> 8;
    int r  = f & 255;
    int ph = r >> 4, pw = r & 15;
    int hp = n / 14, wp = n % 14;
    g_vp[idx] = x[(((size_t)(b * CIN + c)) * IMG + hp * PS + ph) * IMG + wp * PS + pw];
}

// =====================================================================
// tf32 mma.sync GEMM: C[M,N] = A[M,K] @ B[K,N] (+bias) (+gelu | +residual)
// 128x128 block, BK=16, 256 threads (8 warps 2x4), warp tile 64x32.
// Requires N % 128 == 0, K % 16 == 0. M guarded.
// =====================================================================
#define BM 128
#define BN 128
#define BKT 16
#define AST 20      // A smem row stride (floats): 16 + 4 pad
#define BST 136     // B smem row stride (floats): 128 + 8 pad

__device__ __forceinline__ void cp_async16(uint32_t dst, const void* src, int srcBytes) {
    asm volatile("cp.async.ca.shared.global [%0], [%1], 16, %2;\n"
                 :: "r"(dst), "l"(src), "r"(srcBytes));
}
__device__ __forceinline__ void cp_commit() {
    asm volatile("cp.async.commit_group;\n");
}
template<int N_>
__device__ __forceinline__ void cp_wait() {
    asm volatile("cp.async.wait_group %0;\n" :: "n"(N_));
}
__device__ __forceinline__ uint32_t f2tf32(float v) {
    uint32_t r;
    asm("cvt.rna.tf32.f32 %0, %1;\n" : "=r"(r) : "f"(v));
    return r;
}
__device__ __forceinline__ void mma_tf32(float c[4], const uint32_t a[4], const uint32_t b[2]) {
    asm volatile(
        "mma.sync.aligned.m16n8k8.row.col.f32.tf32.tf32.f32 "
        "{%0,%1,%2,%3}, {%4,%5,%6,%7}, {%8,%9}, {%0,%1,%2,%3};\n"
        : "+f"(c[0]), "+f"(c[1]), "+f"(c[2]), "+f"(c[3])
        : "r"(a[0]), "r"(a[1]), "r"(a[2]), "r"(a[3]), "r"(b[0]), "r"(b[1]));
}

template<int EPI>  // 0=bias 1=bias+gelu 2=bias+residual
__global__ __launch_bounds__(256, 2)
void gemm_mma(const float* __restrict__ A, const float* __restrict__ B,
              const float* __restrict__ bias, const float* __restrict__ R,
              float* __restrict__ C, int M, int N, int K)
{
    __shared__ float As[2][BM * AST];
    __shared__ float Bs[2][BKT * BST];

    const int tid  = threadIdx.x;
    const int wid  = tid >> 5;
    const int lane = tid & 31;
    const int g    = lane >> 2;    // groupID
    const int tig  = lane & 3;     // threadID in group
    const int wm   = wid & 1;      // warp row (2)
    const int wn   = wid >> 1;     // warp col (4)
    const int rowBase = blockIdx.y * BM;
    const int colBase = blockIdx.x * BN;

    float acc[4][4][4];
    #pragma unroll
    for (int mt = 0; mt < 4; mt++)
        #pragma unroll
        for (int nt = 0; nt < 4; nt++)
            #pragma unroll
            for (int r = 0; r < 4; r++) acc[mt][nt][r] = 0.f;

    const uint32_t sA = (uint32_t)__cvta_generic_to_shared(&As[0][0]);
    const uint32_t sB = (uint32_t)__cvta_generic_to_shared(&Bs[0][0]);

    // precomputed loader indices
    const int aR0 = tid >> 2, aC0 = tid & 3;          // A: p=0 -> rows 0..63
    const int bR0 = tid >> 5, bC0 = tid & 31;         // B: p=0 -> k-rows 0..7

    const int nIters = K / BKT;

    // ---- prologue: load tile 0 into buf 0 ----
    {
        const int k0 = 0, buf = 0;
        #pragma unroll
        for (int p = 0; p < 2; p++) {
            int r = aR0 + p * 64, cc = aC0;
            int gRow = rowBase + r;
            int srcB = (gRow < M) ? 16 : 0;
            int gClamp = (gRow < M) ? gRow : 0;
            cp_async16(sA + (uint32_t)((buf * BM * AST + r * AST + cc * 4) * 4),
                       A + (size_t)gClamp * K + k0 + cc * 4, srcB);
        }
        #pragma unroll
        for (int p = 0; p < 2; p++) {
            int r = bR0 + p * 8, cc = bC0;
            cp_async16(sB + (uint32_t)((buf * BKT * BST + r * BST + cc * 4) * 4),
                       B + (size_t)(k0 + r) * N + colBase + cc * 4, 16);
        }
        cp_commit();
    }

    for (int it = 0; it < nIters; it++) {
        const int buf = it & 1;
        if (it + 1 < nIters) {
            const int nbuf = buf ^ 1;
            const int k0 = (it + 1) * BKT;
            #pragma unroll
            for (int p = 0; p < 2; p++) {
                int r = aR0 + p * 64, cc = aC0;
                int gRow = rowBase + r;
                int srcB = (gRow < M) ? 16 : 0;
                int gClamp = (gRow < M) ? gRow : 0;
                cp_async16(sA + (uint32_t)((nbuf * BM * AST + r * AST + cc * 4) * 4),
                           A + (size_t)gClamp * K + k0 + cc * 4, srcB);
            }
            #pragma unroll
            for (int p = 0; p < 2; p++) {
                int r = bR0 + p * 8, cc = bC0;
                cp_async16(sB + (uint32_t)((nbuf * BKT * BST + r * BST + cc * 4) * 4),
                           B + (size_t)(k0 + r) * N + colBase + cc * 4, 16);
            }
            cp_commit();
            cp_wait<1>();
        } else {
            cp_wait<0>();
        }
        __syncthreads();

        // ---- compute on buf ----
        #pragma unroll
        for (int ks = 0; ks < 2; ks++) {
            uint32_t bfrag[4][2];
            #pragma unroll
            for (int nt = 0; nt < 4; nt++) {
                int ncol = wn * 32 + nt * 8 + g;
                bfrag[nt][0] = f2tf32(Bs[buf][(ks * 8 + tig)     * BST + ncol]);
                bfrag[nt][1] = f2tf32(Bs[buf][(ks * 8 + tig + 4) * BST + ncol]);
            }
            uint32_t afrag[4][4];
            #pragma unroll
            for (int mt = 0; mt < 4; mt++) {
                int r0 = wm * 64 + mt * 16 + g;
                afrag[mt][0] = f2tf32(As[buf][(r0)     * AST + ks * 8 + tig]);
                afrag[mt][1] = f2tf32(As[buf][(r0 + 8) * AST + ks * 8 + tig]);
                afrag[mt][2] = f2tf32(As[buf][(r0)     * AST + ks * 8 + tig + 4]);
                afrag[mt][3] = f2tf32(As[buf][(r0 + 8) * AST + ks * 8 + tig + 4]);
            }
            #pragma unroll
            for (int mt = 0; mt < 4; mt++)
                #pragma unroll
                for (int nt = 0; nt < 4; nt++)
                    mma_tf32(acc[mt][nt], afrag[mt], bfrag[nt]);
        }
        __syncthreads();
    }

    // ---- epilogue: fused bias / gelu / residual, float2 stores ----
    #pragma unroll
    for (int mt = 0; mt < 4; mt++) {
        int row0 = rowBase + wm * 64 + mt * 16 + g;
        #pragma unroll
        for (int nt = 0; nt < 4; nt++) {
            int col = colBase + wn * 32 + nt * 8 + tig * 2;
            float b0 = bias[col], b1 = bias[col + 1];
            #pragma unroll
            for (int half = 0; half < 2; half++) {
                int row = row0 + half * 8;
                if (row >= M) continue;
                float v0 = acc[mt][nt][half * 2 + 0] + b0;
                float v1 = acc[mt][nt][half * 2 + 1] + b1;
                if (EPI == 1) {
                    v0 = 0.5f * v0 * (1.0f + erff(v0 * 0.70710678118654752f));
                    v1 = 0.5f * v1 * (1.0f + erff(v1 * 0.70710678118654752f));
                }
                if (EPI == 2) {
                    float2 rv = *(const float2*)(R + (size_t)row * N + col);
                    v0 += rv.x; v1 += rv.y;
                }
                float2 o; o.x = v0; o.y = v1;
                *(float2*)(C + (size_t)row * N + col) = o;
            }
        }
    }
}

// ---------------- mask-token assembly + pos embed ----------------
__global__ void assemble(const float* __restrict__ mask_token,
                         const float* __restrict__ pos) {
    int idx = blockIdx.x * blockDim.x + threadIdx.x;
    if (idx >= TOK_FULL * DEC) return;
    int d  = idx & (DEC - 1);
    int bn = idx >> 9;
    int n  = bn % NPATCH;
    int b  = bn / NPATCH;
    int sl = g_slot[bn];
    float v = (sl < 0) ? mask_token[d] : g_dec[(size_t)(b * NVIS + sl) * DEC + d];
    g_h[idx] = v + pos[n * DEC + d];
}

// ---------------- flash-style attention, one block per (b, head) ----------
__global__ __launch_bounds__(224)
void attn_kernel(const float* __restrict__ qkv, float* __restrict__ out) {
    const int S = NPATCH;
    int b = blockIdx.x >> 4;
    int h = blockIdx.x & 15;
    int tid = threadIdx.x;
    __shared__ float Kt[64][HD];
    __shared__ float Vt[64][HD];

    float q[HD];
    const float* qbase = qkv + (size_t)(b * S) * (3 * DEC) + h * HD;
    if (tid < S) {
        const float* qp = qbase + (size_t)tid * (3 * DEC);
        #pragma unroll
        for (int k = 0; k < HD; k++) q[k] = qp[k];
    }
    float o[HD];
    #pragma unroll
    for (int k = 0; k < HD; k++) o[k] = 0.f;
    float m = -1e30f, s = 0.f;
    const float scale = 0.17677669529663689f;

    for (int j0 = 0; j0 < S; j0 += 64) {
        int jn = min(64, S - j0);
        for (int idx = tid; idx < jn * HD; idx += blockDim.x) {
            int jj = idx >> 5, kk = idx & 31;
            const float* base = qkv + (size_t)(b * S + j0 + jj) * (3 * DEC) + h * HD;
            Kt[jj][kk] = base[DEC + kk];
            Vt[jj][kk] = base[2 * DEC + kk];
        }
        __syncthreads();
        if (tid < S) {
            for (int jj = 0; jj < jn; jj++) {
                float d = 0.f;
                #pragma unroll
                for (int k = 0; k < HD; k++) d = fmaf(q[k], Kt[jj][k], d);
                d *= scale;
                float nm = fmaxf(m, d);
                float p    = __expf(d - nm);
                float corr = __expf(m - nm);
                s = s * corr + p;
                #pragma unroll
                for (int k = 0; k < HD; k++) o[k] = fmaf(o[k], corr, p * Vt[jj][k]);
                m = nm;
            }
        }
        __syncthreads();
    }
    if (tid < S) {
        float inv = 1.f / s;
        float* op = out + (size_t)(b * S + tid) * DEC + h * HD;
        #pragma unroll
        for (int k = 0; k < HD; k++) op[k] = o[k] * inv;
    }
}

// ---------------- layernorm over last dim 512 ----------------
__global__ __launch_bounds__(128)
void ln_kernel(const float* __restrict__ X, const float* __restrict__ g,
               const float* __restrict__ bta, float* __restrict__ Y) {
    int row = blockIdx.x;
    int tid = threadIdx.x;
    const float* x = X + (size_t)row * DEC;
    float v[4];
    float sum = 0.f, sq = 0.f;
    #pragma unroll
    for (int i = 0; i < 4; i++) {
        v[i] = x[tid + i * 128];
        sum += v[i];
        sq  += v[i] * v[i];
    }
    #pragma unroll
    for (int o = 16; o > 0; o >>= 1) {
        sum += __shfl_xor_sync(0xffffffffu, sum, o);
        sq  += __shfl_xor_sync(0xffffffffu, sq,  o);
    }
    __shared__ float s1[4], s2[4];
    int w = tid >> 5;
    if ((tid & 31) == 0) { s1[w] = sum; s2[w] = sq; }
    __syncthreads();
    float tot  = s1[0] + s1[1] + s1[2] + s1[3];
    float tot2 = s2[0] + s2[1] + s2[2] + s2[3];
    float mean = tot * (1.f / DEC);
    float var  = tot2 * (1.f / DEC) - mean * mean;
    float r = rsqrtf(var + 1e-5f);
    float* y = Y + (size_t)row * DEC;
    #pragma unroll
    for (int i = 0; i < 4; i++) {
        int c = tid + i * 128;
        y[c] = (v[i] - mean) * r * g[c] + bta[c];
    }
}

// ---------------- host orchestration ----------------
static void launch_gemm(int epi, const float* A, const float* B, const float* bias,
                        const float* R, float* C, int M, int N, int K) {
    dim3 grid(N / 128, (M + 127) / 128);
    if (epi == 0)      gemm_mma<0><<<grid, 256>>>(A, B, bias, R, C, M, N, K);
    else if (epi == 1) gemm_mma<1><<<grid, 256>>>(A, B, bias, R, C, M, N, K);
    else               gemm_mma<2><<<grid, 256>>>(A, B, bias, R, C, M, N, K);
}

extern "C" void kernel_launch(void* const* d_in, const int* in_sizes, int n_in,
                              void* d_out, int out_size) {
    const float* x          = (const float*)d_in[0];
    const void*  mask       = d_in[1];
    const float* Wp         = (const float*)d_in[3];
    const float* bp         = (const float*)d_in[4];
    const float* We2d       = (const float*)d_in[5];
    const float* be2d       = (const float*)d_in[6];
    const float* mask_token = (const float*)d_in[7];
    const float* pos        = (const float*)d_in[8];
    const float* Wqkv       = (const float*)d_in[9];
    const float* bqkv       = (const float*)d_in[10];
    const float* Wo         = (const float*)d_in[11];
    const float* bo         = (const float*)d_in[12];
    const float* ln1g       = (const float*)d_in[13];
    const float* ln1b       = (const float*)d_in[14];
    const float* W1         = (const float*)d_in[15];
    const float* b1         = (const float*)d_in[16];
    const float* W2         = (const float*)d_in[17];
    const float* b2         = (const float*)d_in[18];
    const float* ln2g       = (const float*)d_in[19];
    const float* ln2b       = (const float*)d_in[20];
    const float* Wr         = (const float*)d_in[21];
    const float* br         = (const float*)d_in[22];
    float* out = (float*)d_out;

    float *p_vp, *p_enc, *p_dec, *p_h, *p_qkv, *p_attn, *p_ffn, *p_tmp;
    cudaGetSymbolAddress((void**)&p_vp,  g_vp);
    cudaGetSymbolAddress((void**)&p_enc, g_enc);
    cudaGetSymbolAddress((void**)&p_dec, g_dec);
    cudaGetSymbolAddress((void**)&p_h,   g_h);
    cudaGetSymbolAddress((void**)&p_qkv, g_qkv);
    cudaGetSymbolAddress((void**)&p_attn,g_attn);
    cudaGetSymbolAddress((void**)&p_ffn, g_ffn);
    cudaGetSymbolAddress((void**)&p_tmp, g_tmp);

    detect_mask_mode<<<1, 32>>>(mask);
    build_indices<<<BATCH, 32>>>(mask);

    {
        int total = TOK_VIS * OUTD;
        gather_patches<<<(total + 255) / 256, 256>>>(x);
    }

    // encoder projection: [3136,3072] @ [3072,768]
    launch_gemm(0, p_vp, Wp, bp, nullptr, p_enc, TOK_VIS, ENC, OUTD);
    // enc -> dec: [3136,768] @ [768,512]
    launch_gemm(0, p_enc, We2d, be2d, nullptr, p_dec, TOK_VIS, DEC, ENC);

    {
        int total = TOK_FULL * DEC;
        assemble<<<(total + 255) / 256, 256>>>(mask_token, pos);
    }

    for (int l = 0; l < NLAYERS; l++) {
        const float* Wqkv_l = Wqkv + (size_t)l * DEC * 3 * DEC;
        const float* bqkv_l = bqkv + (size_t)l * 3 * DEC;
        const float* Wo_l   = Wo   + (size_t)l * DEC * DEC;
        const float* bo_l   = bo   + (size_t)l * DEC;
        const float* W1_l   = W1   + (size_t)l * DEC * FFN;
        const float* b1_l   = b1   + (size_t)l * FFN;
        const float* W2_l   = W2   + (size_t)l * FFN * DEC;
        const float* b2_l   = b2   + (size_t)l * DEC;

        launch_gemm(0, p_h, Wqkv_l, bqkv_l, nullptr, p_qkv, TOK_FULL, 3 * DEC, DEC);
        attn_kernel<<<BATCH * NHEADS, 224>>>(p_qkv, p_attn);
        launch_gemm(2, p_attn, Wo_l, bo_l, p_h, p_tmp, TOK_FULL, DEC, DEC);
        ln_kernel<<<TOK_FULL, 128>>>(p_tmp, ln1g + (size_t)l * DEC, ln1b + (size_t)l * DEC, p_h);

        launch_gemm(1, p_h, W1_l, b1_l, nullptr, p_ffn, TOK_FULL, FFN, DEC);
        launch_gemm(2, p_ffn, W2_l, b2_l, p_h, p_tmp, TOK_FULL, DEC, FFN);
        ln_kernel<<<TOK_FULL, 128>>>(p_tmp, ln2g + (size_t)l * DEC, ln2b + (size_t)l * DEC, p_h);
    }

    // reconstruction: [12544,512] @ [512,3072]
    launch_gemm(0, p_h, Wr, br, nullptr, out, TOK_FULL, OUTD, DEC);

    const long long recon_elems = (long long)TOK_FULL * OUTD;
    const long long enc_elems   = (long long)TOK_VIS * ENC;
    if ((long long)out_size >= recon_elems + enc_elems) {
        cudaMemcpyAsync(out + recon_elems, p_enc, enc_elems * sizeof(float),
                        cudaMemcpyDeviceToDevice, 0);
    }
}